// round 10
// baseline (speedup 1.0000x reference)
#include <cuda_runtime.h>
#include <cuda_fp16.h>
#include <cstdint>

// ---------------------------------------------------------------------------
// out[n, e*4+a] = sum_{m,b} adj[n, m*4+b] * Vk[m*4+b, e*4+a]
// C[4096,128] = A[4096,16384] @ Vk.  A fp32 -> fp16 in-kernel, B packed fp16.
// mma.m16n8k16.f16.f32.  Split-K = 9 (uneven) for 288-CTA wave balance.
// ---------------------------------------------------------------------------
#define NODES 4096
#define KTOT  16384
#define NC    128

#define BM 128
#define BK 32
#define SPLITS 9
#define KB_TOTAL (KTOT / BK)    // 512 k-blocks
#define KB_PER   57             // splits 0..7: 57, split 8: 56

// B operand, fp16, fragment-packed per 16-k slab:
//   value B[k][col] at g_Vp[slab*2048 + col*16 + c*4 + j]
//   slab=k>>4, kk=k&15, c=(kk>>1)&3, j=(kk&1)|((kk>>3)<<1)
__device__ __align__(128) __half g_Vp[KTOT * NC];     // 4 MB
__device__ float g_part[SPLITS * NODES * NC];         // 18 MB

// ------------------------------ helpers ------------------------------------
__device__ __forceinline__ uint32_t smem_u32(const void* p) {
    uint32_t a;
    asm("{ .reg .u64 t; cvta.to.shared.u64 t, %1; cvt.u32.u64 %0, t; }"
        : "=r"(a) : "l"(p));
    return a;
}
__device__ __forceinline__ void cp_async16(uint32_t dst, const void* src) {
    asm volatile("cp.async.cg.shared.global [%0], [%1], 16;"
                 :: "r"(dst), "l"(src) : "memory");
}
__device__ __forceinline__ void cp_commit() {
    asm volatile("cp.async.commit_group;" ::: "memory");
}
template <int N>
__device__ __forceinline__ void cp_wait() {
    asm volatile("cp.async.wait_group %0;" :: "n"(N) : "memory");
}
__device__ __forceinline__ void ldmatrix_x4(uint32_t* r, uint32_t addr) {
    asm volatile("ldmatrix.sync.aligned.m8n8.x4.shared.b16 {%0,%1,%2,%3}, [%4];"
                 : "=r"(r[0]), "=r"(r[1]), "=r"(r[2]), "=r"(r[3]) : "r"(addr));
}
__device__ __forceinline__ void mma_f16(float* d, const uint32_t* a,
                                        const uint32_t* b) {
    asm volatile(
        "mma.sync.aligned.m16n8k16.row.col.f32.f16.f16.f32 "
        "{%0,%1,%2,%3}, {%4,%5,%6,%7}, {%8,%9}, {%0,%1,%2,%3};"
        : "+f"(d[0]), "+f"(d[1]), "+f"(d[2]), "+f"(d[3])
        : "r"(a[0]), "r"(a[1]), "r"(a[2]), "r"(a[3]), "r"(b[0]), "r"(b[1]));
}
__device__ __forceinline__ uint32_t cvt_f16x2(float lo, float hi) {
    uint32_t h;
    asm("cvt.rn.f16x2.f32 %0, %1, %2;" : "=r"(h) : "f"(hi), "f"(lo));
    return h;
}

// ---------------------------------------------------------------------------
// prep: 512 blocks x 256 thr; block = 8 nodes (2 slabs).  W cached in regs,
// pre-rotated by a and f32x2-packed; x via broadcast LDS; f32x2 FMA core.
// Identity: acc[b] += x[(a-b)&3] w[b]  ==>  acc_rot[j] += x[j] w_rot[j],
//   w_rot[j] = w[(a-j)&3], acc[b] = acc_rot[(a-b)&3].
// ---------------------------------------------------------------------------
__global__ __launch_bounds__(256) void prep_kernel(const float* __restrict__ x,
                                                   const float* __restrict__ w) {
    __shared__ float xs[1024];                          // 8 nodes x 128 = 4 KB
    __shared__ __align__(16) __half stage[4096];        // 2 slabs x 2048 = 8 KB

    const int t = threadIdx.x;
    const int tc = t & 127;
    const int nh = t >> 7;
    const int a = tc & 3, e = tc >> 2;

    // stage x for 8 nodes: 1024 floats = 256 float4 (one per thread)
    const float4* xsrc = (const float4*)(x + (size_t)blockIdx.x * 1024);
    ((float4*)xs)[t] = xsrc[t];

    // W register cache: pre-rotated, packed as f32x2 pairs (j=0,1 | j=2,3)
    unsigned long long wrot2[32][2];
#pragma unroll
    for (int d = 0; d < 32; d++) {
        float wv0 = __ldg(w + d * 128 + e * 4 + (a & 3));
        float wv1 = __ldg(w + d * 128 + e * 4 + ((a - 1) & 3));
        float wv2 = __ldg(w + d * 128 + e * 4 + ((a - 2) & 3));
        float wv3 = __ldg(w + d * 128 + e * 4 + ((a - 3) & 3));
        asm("mov.b64 %0, {%1, %2};" : "=l"(wrot2[d][0]) : "f"(wv0), "f"(wv1));
        asm("mov.b64 %0, {%1, %2};" : "=l"(wrot2[d][1]) : "f"(wv2), "f"(wv3));
    }
    __syncthreads();

#pragma unroll
    for (int i = 0; i < 4; i++) {
        const int ml = nh * 4 + i;                      // node 0..7 in block
        const unsigned long long* xp =
            (const unsigned long long*)(xs + ml * 128);
        unsigned long long acc2[2] = {0ULL, 0ULL};      // {0.f,0.f} packed
#pragma unroll
        for (int d = 0; d < 32; d++) {
            const unsigned long long xv0 = xp[d * 2];
            const unsigned long long xv1 = xp[d * 2 + 1];
            asm("fma.rn.f32x2 %0, %1, %2, %0;"
                : "+l"(acc2[0]) : "l"(xv0), "l"(wrot2[d][0]));
            asm("fma.rn.f32x2 %0, %1, %2, %0;"
                : "+l"(acc2[1]) : "l"(xv1), "l"(wrot2[d][1]));
        }
        float ar[4];
        asm("mov.b64 {%0, %1}, %2;" : "=f"(ar[0]), "=f"(ar[1]) : "l"(acc2[0]));
        asm("mov.b64 {%0, %1}, %2;" : "=f"(ar[2]), "=f"(ar[3]) : "l"(acc2[1]));

        const int mi = ml & 3;                          // node within slab
        __half* sb = stage + (ml >> 2) * 2048 + tc * 16;
#pragma unroll
        for (int jp = 0; jp < 4; jp++) {
            const int b = (a - jp) & 3;
            const int kk = mi * 4 + b;
            const int cc = (kk >> 1) & 3;
            const int jj = (kk & 1) | ((kk >> 3) << 1);
            sb[cc * 4 + jj] = __float2half_rn(ar[jp]);
        }
    }
    __syncthreads();

    // coalesced copy-out: 2 slabs x 2048 halfs = 8192 B = 512 uint4
    uint4* dst = (uint4*)(g_Vp + (size_t)blockIdx.x * (2 * 2048));
    const uint4* srcs = (const uint4*)stage;
    dst[t] = srcs[t];
    dst[t + 256] = srcs[t + 256];
}

// ---------------------------------------------------------------------------
// GEMM: grid (32 m-tiles, 9 splits), 256 thr = 8 warps (4m x 2n),
// warp tile 32x64, mma m16n8k16 f16.f32.  (unchanged, validated)
// ---------------------------------------------------------------------------
__global__ __launch_bounds__(256, 2) void gemm_kernel(const float* __restrict__ A) {
    __shared__ __align__(16) __half Asm[2][128 * 32];   // 16 KB, swizzled
    __shared__ __align__(16) __half Bsm[3][32 * 128];   // 24 KB, packed

    const uint32_t asb = smem_u32(Asm);
    const uint32_t bsb = smem_u32(Bsm);
    const int tid = threadIdx.x;
    const int lane = tid & 31;
    const int wid = tid >> 5;
    const int wm = (wid & 3) * 32;
    const int wn = (wid >> 2) * 64;
    const int g = lane >> 2;
    const int c = lane & 3;

    const int m0 = blockIdx.x * BM;
    const int kb0 = blockIdx.y * KB_PER;
    const int cnt = min(KB_PER, KB_TOTAL - kb0);
    const int k0 = kb0 * BK;
    const __half* Bsrc = g_Vp + (size_t)(k0 >> 4) * 2048;

    const int row_l = (lane & 7) | (((lane >> 3) & 1) << 3);
    const int khalf = lane >> 4;
    uint32_t a_addr[2][2];
#pragma unroll
    for (int mi = 0; mi < 2; mi++)
#pragma unroll
        for (int ks = 0; ks < 2; ks++) {
            const int r = wm + mi * 16 + row_l;
            const int ch = (ks * 2 + khalf) ^ (r & 3);
            a_addr[mi][ks] = asb + (uint32_t)(r * 64 + ch * 16);
        }
    const uint32_t b_off = (uint32_t)((wn + g) * 32 + c * 8);

    const int a_row = tid >> 3;
    const int a_kq = tid & 7;

    float acc[2][8][4];
#pragma unroll
    for (int mi = 0; mi < 2; mi++)
#pragma unroll
        for (int ni = 0; ni < 8; ni++)
#pragma unroll
            for (int j = 0; j < 4; j++) acc[mi][ni][j] = 0.f;

    float4 pf[4];
    auto ldgA = [&](int it) {
        if (it < cnt) {
            const int ko = k0 + it * BK;
#pragma unroll
            for (int p = 0; p < 4; p++)
                pf[p] = *(const float4*)(A + (size_t)(m0 + a_row + p * 32) * KTOT +
                                         ko + a_kq * 4);
        }
    };
    auto stsA = [&](int it) {
        if (it < cnt) {
            const uint32_t base = asb + (uint32_t)(it & 1) * 8192u;
#pragma unroll
            for (int p = 0; p < 4; p++) {
                const int row = a_row + p * 32;
                const uint32_t off =
                    (uint32_t)(row * 64 + (((a_kq >> 1) ^ (row & 3)) * 16) +
                               (a_kq & 1) * 8);
                const uint32_t h0 = cvt_f16x2(pf[p].x, pf[p].y);
                const uint32_t h1 = cvt_f16x2(pf[p].z, pf[p].w);
                asm volatile("st.shared.v2.b32 [%0], {%1, %2};"
                             :: "r"(base + off), "r"(h0), "r"(h1) : "memory");
            }
        }
    };
    auto cpB = [&](int it) {
        if (it < cnt) {
            const uint32_t bd = bsb + (uint32_t)(it % 3) * 8192u;
            const char* src = (const char*)(Bsrc + (size_t)it * 4096);
#pragma unroll
            for (int p = 0; p < 2; p++) {
                const int idx = tid + p * 256;
                cp_async16(bd + (uint32_t)idx * 16, src + idx * 16);
            }
        }
    };

    // prologue
    ldgA(0);
    cpB(0); cp_commit();
    cpB(1); cp_commit();
    stsA(0);
    ldgA(1);

    for (int it = 0; it < cnt; it++) {
        cp_wait<1>();
        __syncthreads();

        cpB(it + 2); cp_commit();
        stsA(it + 1);
        ldgA(it + 2);

        const uint32_t a_st = (uint32_t)(it & 1) * 8192u;
        const uint32_t b_st = bsb + (uint32_t)(it % 3) * 8192u + b_off;
#pragma unroll
        for (int ks = 0; ks < 2; ks++) {
            uint32_t af[2][4];
            ldmatrix_x4(af[0], a_addr[0][ks] + a_st);
            ldmatrix_x4(af[1], a_addr[1][ks] + a_st);
            uint32_t bf[8][2];
#pragma unroll
            for (int ni = 0; ni < 8; ni++)
                asm volatile("ld.shared.v2.b32 {%0, %1}, [%2];"
                             : "=r"(bf[ni][0]), "=r"(bf[ni][1])
                             : "r"(b_st + (uint32_t)(ks * 4096 + ni * 256)));
#pragma unroll
            for (int mi = 0; mi < 2; mi++)
#pragma unroll
                for (int ni = 0; ni < 8; ni++)
                    mma_f16(acc[mi][ni], af[mi], bf[ni]);
        }
    }

    // epilogue -> split-K partials
    float* outp = g_part + (size_t)blockIdx.y * (NODES * NC);
#pragma unroll
    for (int mi = 0; mi < 2; mi++) {
        const int row = m0 + wm + mi * 16 + g;
#pragma unroll
        for (int ni = 0; ni < 8; ni++) {
            const int col = wn + ni * 8 + 2 * c;
            *(float2*)&outp[(size_t)row * NC + col] =
                make_float2(acc[mi][ni][0], acc[mi][ni][1]);
            *(float2*)&outp[(size_t)(row + 8) * NC + col] =
                make_float2(acc[mi][ni][2], acc[mi][ni][3]);
        }
    }
}

// ---------------------------------------------------------------------------
__global__ __launch_bounds__(256) void reduce_kernel(float* __restrict__ out) {
    const int i4 = (blockIdx.x * 256 + threadIdx.x) * 4;
    float4 s = make_float4(0.f, 0.f, 0.f, 0.f);
#pragma unroll
    for (int p = 0; p < SPLITS; p++) {
        const float4 v = *(const float4*)&g_part[(size_t)p * (NODES * NC) + i4];
        s.x += v.x; s.y += v.y; s.z += v.z; s.w += v.w;
    }
    *(float4*)&out[i4] = s;
}

// ---------------------------------------------------------------------------
extern "C" void kernel_launch(void* const* d_in, const int* in_sizes, int n_in,
                              void* d_out, int out_size) {
    const float* x   = (const float*)d_in[0];   // (4096, 32, 4)
    const float* adj = (const float*)d_in[1];   // (4096, 4096, 4)
    const float* w   = (const float*)d_in[2];   // (32, 32, 4)
    float* out = (float*)d_out;                 // (4096, 32, 4)
    (void)in_sizes; (void)n_in; (void)out_size;

    prep_kernel<<<512, 256>>>(x, w);
    gemm_kernel<<<dim3(NODES / BM, SPLITS), 256>>>(adj);
    reduce_kernel<<<(NODES * NC) / 1024, 256>>>(out);
}

// round 11
// speedup vs baseline: 1.0255x; 1.0255x over previous
#include <cuda_runtime.h>
#include <cuda_fp16.h>
#include <cstdint>

// ---------------------------------------------------------------------------
// out[n, e*4+a] = sum_{m,b} adj[n, m*4+b] * Vk[m*4+b, e*4+a]
// C[4096,128] = A[4096,16384] @ Vk.  A fp32 -> fp16 in-kernel, B packed fp16.
// mma.m16n8k16.f16.f32.  Split-K = 9 (uneven) for 288-CTA wave balance.
// ---------------------------------------------------------------------------
#define NODES 4096
#define KTOT  16384
#define NC    128

#define BM 128
#define BK 32
#define SPLITS 9
#define KB_TOTAL (KTOT / BK)    // 512 k-blocks
#define KB_PER   57             // splits 0..7: 57, split 8: 56

// B operand, fp16, fragment-packed per 16-k slab:
//   value B[k][col] at g_Vp[slab*2048 + col*16 + c*4 + j]
//   slab=k>>4, kk=k&15, c=(kk>>1)&3, j=(kk&1)|((kk>>3)<<1)
__device__ __align__(128) __half g_Vp[KTOT * NC];     // 4 MB
__device__ float g_part[SPLITS * NODES * NC];         // 18 MB

// ------------------------------ helpers ------------------------------------
__device__ __forceinline__ uint32_t smem_u32(const void* p) {
    uint32_t a;
    asm("{ .reg .u64 t; cvta.to.shared.u64 t, %1; cvt.u32.u64 %0, t; }"
        : "=r"(a) : "l"(p));
    return a;
}
__device__ __forceinline__ void cp_async16(uint32_t dst, const void* src) {
    asm volatile("cp.async.cg.shared.global [%0], [%1], 16;"
                 :: "r"(dst), "l"(src) : "memory");
}
__device__ __forceinline__ void cp_commit() {
    asm volatile("cp.async.commit_group;" ::: "memory");
}
template <int N>
__device__ __forceinline__ void cp_wait() {
    asm volatile("cp.async.wait_group %0;" :: "n"(N) : "memory");
}
__device__ __forceinline__ void ldmatrix_x4(uint32_t* r, uint32_t addr) {
    asm volatile("ldmatrix.sync.aligned.m8n8.x4.shared.b16 {%0,%1,%2,%3}, [%4];"
                 : "=r"(r[0]), "=r"(r[1]), "=r"(r[2]), "=r"(r[3]) : "r"(addr));
}
__device__ __forceinline__ void mma_f16(float* d, const uint32_t* a,
                                        const uint32_t* b) {
    asm volatile(
        "mma.sync.aligned.m16n8k16.row.col.f32.f16.f16.f32 "
        "{%0,%1,%2,%3}, {%4,%5,%6,%7}, {%8,%9}, {%0,%1,%2,%3};"
        : "+f"(d[0]), "+f"(d[1]), "+f"(d[2]), "+f"(d[3])
        : "r"(a[0]), "r"(a[1]), "r"(a[2]), "r"(a[3]), "r"(b[0]), "r"(b[1]));
}
__device__ __forceinline__ uint32_t cvt_f16x2(float lo, float hi) {
    uint32_t h;
    asm("cvt.rn.f16x2.f32 %0, %1, %2;" : "=r"(h) : "f"(hi), "f"(lo));
    return h;
}

// ---------------------------------------------------------------------------
// prep: 512 blocks x 256 thr; thread = (node nl 0..7, e 0..31).
// W in smem; per d one float4 of x (broadcast) + one float4 of w serves all
// 16 (a,b) products: acc[a][b] += x4[(a-b)&3] * w4[b]  (compile-time lanes).
// ---------------------------------------------------------------------------
__global__ __launch_bounds__(256) void prep_kernel(const float* __restrict__ x,
                                                   const float* __restrict__ w) {
    __shared__ float ws[4096];                          // full W, 16 KB
    __shared__ float xs[1024];                          // 8 nodes x 128, 4 KB
    __shared__ __align__(16) __half stage[4096];        // 2 slabs x 2048, 8 KB

    const int t = threadIdx.x;
    const int nl = t >> 5;                              // node local 0..7
    const int e = t & 31;

    // stage W (4096 floats = 1024 float4) and x (1024 floats = 256 float4)
#pragma unroll
    for (int i = 0; i < 4; i++)
        ((float4*)ws)[t + i * 256] = ((const float4*)w)[t + i * 256];
    ((float4*)xs)[t] =
        ((const float4*)(x + (size_t)blockIdx.x * 1024))[t];
    __syncthreads();

    float acc[4][4];
#pragma unroll
    for (int a = 0; a < 4; a++)
#pragma unroll
        for (int b = 0; b < 4; b++) acc[a][b] = 0.f;

#pragma unroll
    for (int d = 0; d < 32; d++) {
        const float4 xv = *(const float4*)&xs[nl * 128 + d * 4];
        const float4 wv = *(const float4*)&ws[d * 128 + e * 4];
        const float xc[4] = {xv.x, xv.y, xv.z, xv.w};
        const float wc[4] = {wv.x, wv.y, wv.z, wv.w};
#pragma unroll
        for (int a = 0; a < 4; a++)
#pragma unroll
            for (int b = 0; b < 4; b++)
                acc[a][b] += xc[(a - b) & 3] * wc[b];
    }

    // pack into fragment layout: for (mi=nl&3, a): kk=4*mi+b
    //   b=0,1 -> cc=(2*mi)&3,   jj=(mi>>1)*2 + b
    //   b=2,3 -> cc=(2*mi+1)&3, jj=(mi>>1)*2 + (b&1)
    {
        const int mi = nl & 3;
        const int jjb = (mi >> 1) * 2;
        const int cc0 = (2 * mi) & 3, cc1 = (2 * mi + 1) & 3;
        __half* sb = stage + (nl >> 2) * 2048;
#pragma unroll
        for (int a = 0; a < 4; a++) {
            const int col = e * 4 + a;
            *(__half2*)&sb[col * 16 + cc0 * 4 + jjb] =
                __floats2half2_rn(acc[a][0], acc[a][1]);
            *(__half2*)&sb[col * 16 + cc1 * 4 + jjb] =
                __floats2half2_rn(acc[a][2], acc[a][3]);
        }
    }
    __syncthreads();

    // coalesced copy-out: 2 slabs x 2048 halfs = 8192 B = 512 uint4
    uint4* dst = (uint4*)(g_Vp + (size_t)blockIdx.x * (2 * 2048));
    const uint4* srcs = (const uint4*)stage;
    dst[t] = srcs[t];
    dst[t + 256] = srcs[t + 256];
}

// ---------------------------------------------------------------------------
// GEMM: grid (32 m-tiles, 9 splits), 256 thr = 8 warps (4m x 2n),
// warp tile 32x64, mma m16n8k16 f16.f32.  (unchanged, validated R9)
// ---------------------------------------------------------------------------
__global__ __launch_bounds__(256, 2) void gemm_kernel(const float* __restrict__ A) {
    __shared__ __align__(16) __half Asm[2][128 * 32];   // 16 KB, swizzled
    __shared__ __align__(16) __half Bsm[3][32 * 128];   // 24 KB, packed

    const uint32_t asb = smem_u32(Asm);
    const uint32_t bsb = smem_u32(Bsm);
    const int tid = threadIdx.x;
    const int lane = tid & 31;
    const int wid = tid >> 5;
    const int wm = (wid & 3) * 32;
    const int wn = (wid >> 2) * 64;
    const int g = lane >> 2;
    const int c = lane & 3;

    const int m0 = blockIdx.x * BM;
    const int kb0 = blockIdx.y * KB_PER;
    const int cnt = min(KB_PER, KB_TOTAL - kb0);
    const int k0 = kb0 * BK;
    const __half* Bsrc = g_Vp + (size_t)(k0 >> 4) * 2048;

    const int row_l = (lane & 7) | (((lane >> 3) & 1) << 3);
    const int khalf = lane >> 4;
    uint32_t a_addr[2][2];
#pragma unroll
    for (int mi = 0; mi < 2; mi++)
#pragma unroll
        for (int ks = 0; ks < 2; ks++) {
            const int r = wm + mi * 16 + row_l;
            const int ch = (ks * 2 + khalf) ^ (r & 3);
            a_addr[mi][ks] = asb + (uint32_t)(r * 64 + ch * 16);
        }
    const uint32_t b_off = (uint32_t)((wn + g) * 32 + c * 8);

    const int a_row = tid >> 3;
    const int a_kq = tid & 7;

    float acc[2][8][4];
#pragma unroll
    for (int mi = 0; mi < 2; mi++)
#pragma unroll
        for (int ni = 0; ni < 8; ni++)
#pragma unroll
            for (int j = 0; j < 4; j++) acc[mi][ni][j] = 0.f;

    float4 pf[4];
    auto ldgA = [&](int it) {
        if (it < cnt) {
            const int ko = k0 + it * BK;
#pragma unroll
            for (int p = 0; p < 4; p++)
                pf[p] = *(const float4*)(A + (size_t)(m0 + a_row + p * 32) * KTOT +
                                         ko + a_kq * 4);
        }
    };
    auto stsA = [&](int it) {
        if (it < cnt) {
            const uint32_t base = asb + (uint32_t)(it & 1) * 8192u;
#pragma unroll
            for (int p = 0; p < 4; p++) {
                const int row = a_row + p * 32;
                const uint32_t off =
                    (uint32_t)(row * 64 + (((a_kq >> 1) ^ (row & 3)) * 16) +
                               (a_kq & 1) * 8);
                const uint32_t h0 = cvt_f16x2(pf[p].x, pf[p].y);
                const uint32_t h1 = cvt_f16x2(pf[p].z, pf[p].w);
                asm volatile("st.shared.v2.b32 [%0], {%1, %2};"
                             :: "r"(base + off), "r"(h0), "r"(h1) : "memory");
            }
        }
    };
    auto cpB = [&](int it) {
        if (it < cnt) {
            const uint32_t bd = bsb + (uint32_t)(it % 3) * 8192u;
            const char* src = (const char*)(Bsrc + (size_t)it * 4096);
#pragma unroll
            for (int p = 0; p < 2; p++) {
                const int idx = tid + p * 256;
                cp_async16(bd + (uint32_t)idx * 16, src + idx * 16);
            }
        }
    };

    // prologue
    ldgA(0);
    cpB(0); cp_commit();
    cpB(1); cp_commit();
    stsA(0);
    ldgA(1);

    for (int it = 0; it < cnt; it++) {
        cp_wait<1>();
        __syncthreads();

        cpB(it + 2); cp_commit();
        stsA(it + 1);
        ldgA(it + 2);

        const uint32_t a_st = (uint32_t)(it & 1) * 8192u;
        const uint32_t b_st = bsb + (uint32_t)(it % 3) * 8192u + b_off;
#pragma unroll
        for (int ks = 0; ks < 2; ks++) {
            uint32_t af[2][4];
            ldmatrix_x4(af[0], a_addr[0][ks] + a_st);
            ldmatrix_x4(af[1], a_addr[1][ks] + a_st);
            uint32_t bf[8][2];
#pragma unroll
            for (int ni = 0; ni < 8; ni++)
                asm volatile("ld.shared.v2.b32 {%0, %1}, [%2];"
                             : "=r"(bf[ni][0]), "=r"(bf[ni][1])
                             : "r"(b_st + (uint32_t)(ks * 4096 + ni * 256)));
#pragma unroll
            for (int mi = 0; mi < 2; mi++)
#pragma unroll
                for (int ni = 0; ni < 8; ni++)
                    mma_f16(acc[mi][ni], af[mi], bf[ni]);
        }
    }

    // epilogue -> split-K partials
    float* outp = g_part + (size_t)blockIdx.y * (NODES * NC);
#pragma unroll
    for (int mi = 0; mi < 2; mi++) {
        const int row = m0 + wm + mi * 16 + g;
#pragma unroll
        for (int ni = 0; ni < 8; ni++) {
            const int col = wn + ni * 8 + 2 * c;
            *(float2*)&outp[(size_t)row * NC + col] =
                make_float2(acc[mi][ni][0], acc[mi][ni][1]);
            *(float2*)&outp[(size_t)(row + 8) * NC + col] =
                make_float2(acc[mi][ni][2], acc[mi][ni][3]);
        }
    }
}

// ---------------------------------------------------------------------------
__global__ __launch_bounds__(256) void reduce_kernel(float* __restrict__ out) {
    const int i4 = (blockIdx.x * 256 + threadIdx.x) * 4;
    float4 s = make_float4(0.f, 0.f, 0.f, 0.f);
#pragma unroll
    for (int p = 0; p < SPLITS; p++) {
        const float4 v = *(const float4*)&g_part[(size_t)p * (NODES * NC) + i4];
        s.x += v.x; s.y += v.y; s.z += v.z; s.w += v.w;
    }
    *(float4*)&out[i4] = s;
}

// ---------------------------------------------------------------------------
extern "C" void kernel_launch(void* const* d_in, const int* in_sizes, int n_in,
                              void* d_out, int out_size) {
    const float* x   = (const float*)d_in[0];   // (4096, 32, 4)
    const float* adj = (const float*)d_in[1];   // (4096, 4096, 4)
    const float* w   = (const float*)d_in[2];   // (32, 32, 4)
    float* out = (float*)d_out;                 // (4096, 32, 4)
    (void)in_sizes; (void)n_in; (void)out_size;

    prep_kernel<<<512, 256>>>(x, w);
    gemm_kernel<<<dim3(NODES / BM, SPLITS), 256>>>(adj);
    reduce_kernel<<<(NODES * NC) / 1024, 256>>>(out);
}